// round 3
// baseline (speedup 1.0000x reference)
#include <cuda_runtime.h>
#include <math.h>

#define N_ROWS 131072
#define D      2048
#define NT     256            // threads per block
#define CPT    8              // columns per thread = D / NT
#define NBLK   296            // persistent grid = 2 * 148 SMs (all co-resident)
#define RB     4              // rows per batch
#define NBATCH (N_ROWS / RB)  // 32768
#define NCOMB  (D / NT)       // 8 combine blocks
#define INV_T  10.0f          // 1 / temperature
#define EPS    1e-8f

// Scratch (device globals: no allocations allowed)
__device__ float g_pacc[(size_t)NBLK * D];   // per-block partial weighted sums
__device__ float g_pm[NBLK];
__device__ float g_pl[NBLK];
__device__ unsigned int g_count;             // arrival counter (reset each launch)

__global__ void dsdm_reset() { g_count = 0u; }

// ---------------------------------------------------------------------------
// Fused persistent kernel: flash-style online softmin (double-buffered,
// prefetch over barriers) + device-wide arrival barrier + fused LSE-merge
// and column combine in blocks 0..NCOMB-1.
// ---------------------------------------------------------------------------
__global__ __launch_bounds__(NT, 2) void dsdm_main(const float* __restrict__ A,
                                                   const float* __restrict__ q,
                                                   float* __restrict__ out) {
    __shared__ float s_dot[8][RB];
    __shared__ float s_sq[8][RB];
    __shared__ float s_logit[RB];
    __shared__ float s_tmp[8];
    __shared__ float s_scale[NBLK];

    const int tid  = threadIdx.x;
    const int wid  = tid >> 5;
    const int lane = tid & 31;
    const int bid  = blockIdx.x;

    // --- q slice + ||q|| ---
    float qv[CPT];
    {
        const float4 q0 = reinterpret_cast<const float4*>(q)[tid * 2 + 0];
        const float4 q1 = reinterpret_cast<const float4*>(q)[tid * 2 + 1];
        qv[0] = q0.x; qv[1] = q0.y; qv[2] = q0.z; qv[3] = q0.w;
        qv[4] = q1.x; qv[5] = q1.y; qv[6] = q1.z; qv[7] = q1.w;
    }
    float qsq = 0.f;
    #pragma unroll
    for (int i = 0; i < CPT; i++) qsq += qv[i] * qv[i];
    #pragma unroll
    for (int o = 16; o; o >>= 1) qsq += __shfl_xor_sync(0xffffffffu, qsq, o);
    if (lane == 0) s_tmp[wid] = qsq;
    __syncthreads();
    if (tid == 0) {
        float s = 0.f;
        #pragma unroll
        for (int w = 0; w < 8; w++) s += s_tmp[w];
        s_tmp[0] = sqrtf(s);
    }
    __syncthreads();
    const float qn = s_tmp[0];
    __syncthreads();

    float acc[CPT];
    #pragma unroll
    for (int i = 0; i < CPT; i++) acc[i] = 0.f;
    float m = -1e30f;
    float l = 0.f;

    // double-buffered row registers: RB rows x 2 float4 each
    float4 bA0[RB], bA1[RB], bB0[RB], bB1[RB];

#define LOAD_BATCH(v0, v1, batch)                                             \
    {                                                                         \
        _Pragma("unroll")                                                     \
        for (int r = 0; r < RB; r++) {                                        \
            const float4* rp = reinterpret_cast<const float4*>(               \
                A + ((size_t)(batch) * RB + r) * D) + tid * 2;                \
            v0[r] = __ldcs(rp + 0);                                           \
            v1[r] = __ldcs(rp + 1);                                           \
        }                                                                     \
    }

#define PROCESS(v0, v1)                                                       \
    {                                                                         \
        float dt[RB], sq[RB];                                                 \
        _Pragma("unroll")                                                     \
        for (int r = 0; r < RB; r++) {                                        \
            float d = v0[r].x * qv[0] + v0[r].y * qv[1] +                     \
                      v0[r].z * qv[2] + v0[r].w * qv[3] +                     \
                      v1[r].x * qv[4] + v1[r].y * qv[5] +                     \
                      v1[r].z * qv[6] + v1[r].w * qv[7];                      \
            float s = v0[r].x * v0[r].x + v0[r].y * v0[r].y +                 \
                      v0[r].z * v0[r].z + v0[r].w * v0[r].w +                 \
                      v1[r].x * v1[r].x + v1[r].y * v1[r].y +                 \
                      v1[r].z * v1[r].z + v1[r].w * v1[r].w;                  \
            dt[r] = d; sq[r] = s;                                             \
        }                                                                     \
        _Pragma("unroll")                                                     \
        for (int r = 0; r < RB; r++) {                                        \
            _Pragma("unroll")                                                 \
            for (int o = 16; o; o >>= 1) {                                    \
                dt[r] += __shfl_xor_sync(0xffffffffu, dt[r], o);              \
                sq[r] += __shfl_xor_sync(0xffffffffu, sq[r], o);              \
            }                                                                 \
        }                                                                     \
        if (lane == 0) {                                                      \
            _Pragma("unroll")                                                 \
            for (int r = 0; r < RB; r++) {                                    \
                s_dot[wid][r] = dt[r]; s_sq[wid][r] = sq[r];                  \
            }                                                                 \
        }                                                                     \
        __syncthreads();                                                      \
        if (tid < RB) {                                                       \
            float d = 0.f, s = 0.f;                                           \
            _Pragma("unroll")                                                 \
            for (int w = 0; w < 8; w++) { d += s_dot[w][tid]; s += s_sq[w][tid]; } \
            s_logit[tid] = (d / fmaxf(sqrtf(s) * qn, EPS)) * INV_T;           \
        }                                                                     \
        __syncthreads();                                                      \
        _Pragma("unroll")                                                     \
        for (int r = 0; r < RB; r++) {                                        \
            const float lg = s_logit[r];                                      \
            const float mn = fmaxf(m, lg);                                    \
            const float cs = __expf(m - mn);                                  \
            const float w  = __expf(lg - mn);                                 \
            m = mn;                                                           \
            l = l * cs + w;                                                   \
            acc[0] = acc[0] * cs + w * v0[r].x;                               \
            acc[1] = acc[1] * cs + w * v0[r].y;                               \
            acc[2] = acc[2] * cs + w * v0[r].z;                               \
            acc[3] = acc[3] * cs + w * v0[r].w;                               \
            acc[4] = acc[4] * cs + w * v1[r].x;                               \
            acc[5] = acc[5] * cs + w * v1[r].y;                               \
            acc[6] = acc[6] * cs + w * v1[r].z;                               \
            acc[7] = acc[7] * cs + w * v1[r].w;                               \
        }                                                                     \
    }

    // --- grid-stride pipeline over batches, unrolled x2 for reg buffers ---
    int batch = bid;
    bool valid = (batch < NBATCH);
    if (valid) LOAD_BATCH(bA0, bA1, batch);

    while (valid) {
        int nb = batch + NBLK;
        bool vnext = (nb < NBATCH);
        if (vnext) LOAD_BATCH(bB0, bB1, nb);   // prefetch flies over barriers
        PROCESS(bA0, bA1);
        batch = nb; valid = vnext;
        if (!valid) break;

        nb = batch + NBLK;
        vnext = (nb < NBATCH);
        if (vnext) LOAD_BATCH(bA0, bA1, nb);
        PROCESS(bB0, bB1);
        batch = nb; valid = vnext;
    }
#undef LOAD_BATCH
#undef PROCESS

    // --- publish partials ---
    if (tid == 0) { g_pm[bid] = m; g_pl[bid] = l; }
    {
        float4* pa = reinterpret_cast<float4*>(g_pacc + (size_t)bid * D) + tid * 2;
        pa[0] = make_float4(acc[0], acc[1], acc[2], acc[3]);
        pa[1] = make_float4(acc[4], acc[5], acc[6], acc[7]);
    }
    __threadfence();
    __syncthreads();
    if (tid == 0) atomicAdd(&g_count, 1u);

    // --- only the first NCOMB blocks finalize ---
    if (bid >= NCOMB) return;

    if (tid == 0) {
        while (atomicAdd(&g_count, 0u) < NBLK) __nanosleep(64);
    }
    __syncthreads();
    __threadfence();

    // Global max of per-block maxima
    float mloc = -1e30f;
    for (int j = tid; j < NBLK; j += NT) mloc = fmaxf(mloc, g_pm[j]);
    #pragma unroll
    for (int o = 16; o; o >>= 1) mloc = fmaxf(mloc, __shfl_xor_sync(0xffffffffu, mloc, o));
    if (lane == 0) s_tmp[wid] = mloc;
    __syncthreads();
    float M;
    {
        float v = s_tmp[lane & 7];
        #pragma unroll
        for (int o = 4; o; o >>= 1) v = fmaxf(v, __shfl_xor_sync(0xffffffffu, v, o));
        M = __shfl_sync(0xffffffffu, v, 0);
    }
    __syncthreads();

    // Global L
    float lloc = 0.f;
    for (int j = tid; j < NBLK; j += NT) lloc += __expf(g_pm[j] - M) * g_pl[j];
    #pragma unroll
    for (int o = 16; o; o >>= 1) lloc += __shfl_xor_sync(0xffffffffu, lloc, o);
    if (lane == 0) s_tmp[wid] = lloc;
    __syncthreads();
    float L;
    {
        float v = s_tmp[lane & 7];
        #pragma unroll
        for (int o = 4; o; o >>= 1) v += __shfl_xor_sync(0xffffffffu, v, o);
        L = __shfl_sync(0xffffffffu, v, 0);
    }
    __syncthreads();

    const float invL = 1.0f / L;
    for (int j = tid; j < NBLK; j += NT) s_scale[j] = __expf(g_pm[j] - M) * invL;
    __syncthreads();

    // Combine this block's 256-column slice (partials are hot in L2)
    const int col = bid * NT + tid;
    float s = 0.f;
    #pragma unroll 8
    for (int j = 0; j < NBLK; j++) {
        s += s_scale[j] * g_pacc[(size_t)j * D + col];
    }
    out[col] = s;
}

extern "C" void kernel_launch(void* const* d_in, const int* in_sizes, int n_in,
                              void* d_out, int out_size) {
    const float* addresses = (const float*)d_in[0];   // [131072, 2048] f32
    const float* query     = (const float*)d_in[1];   // [2048] f32
    float* out = (float*)d_out;                       // [2048] f32

    dsdm_reset<<<1, 1>>>();
    dsdm_main<<<NBLK, NT>>>(addresses, query, out);
}

// round 4
// speedup vs baseline: 1.0698x; 1.0698x over previous
#include <cuda_runtime.h>
#include <math.h>

#define N_ROWS 131072
#define D      2048
#define NT     256            // threads per block
#define CPT    8              // columns per thread = D / NT
#define NBLK   296            // persistent grid = 2 * 148 SMs
#define RB     4              // rows per batch
#define NBATCH (N_ROWS / RB)  // 32768
#define NBY    37             // b-chunks in finalize (296 = 8 * 37)
#define BCH    (NBLK / NBY)   // 8 partials per finalize block
#define INV_T  10.0f          // 1 / temperature
#define EPS    1e-8f

// Scratch (device globals: no allocations allowed)
__device__ float g_pacc[(size_t)NBLK * D];   // per-block partial weighted sums
__device__ float g_pm[NBLK];
__device__ float g_pl[NBLK];
__device__ float g_scale[NBLK];

// ---------------------------------------------------------------------------
// Main persistent kernel: flash-style online softmin, double-buffered loads.
// (Exact R2 configuration: no register cap, plain LDG.128 loads.)
// ---------------------------------------------------------------------------
__global__ __launch_bounds__(NT) void dsdm_main(const float* __restrict__ A,
                                                const float* __restrict__ q) {
    __shared__ float s_dot[8][RB];
    __shared__ float s_sq[8][RB];
    __shared__ float s_logit[RB];
    __shared__ float s_tmp[8];

    const int tid  = threadIdx.x;
    const int wid  = tid >> 5;
    const int lane = tid & 31;

    // --- q slice + ||q|| ---
    float qv[CPT];
    {
        const float4 q0 = reinterpret_cast<const float4*>(q)[tid * 2 + 0];
        const float4 q1 = reinterpret_cast<const float4*>(q)[tid * 2 + 1];
        qv[0] = q0.x; qv[1] = q0.y; qv[2] = q0.z; qv[3] = q0.w;
        qv[4] = q1.x; qv[5] = q1.y; qv[6] = q1.z; qv[7] = q1.w;
    }
    float qsq = 0.f;
    #pragma unroll
    for (int i = 0; i < CPT; i++) qsq += qv[i] * qv[i];
    #pragma unroll
    for (int o = 16; o; o >>= 1) qsq += __shfl_xor_sync(0xffffffffu, qsq, o);
    if (lane == 0) s_tmp[wid] = qsq;
    __syncthreads();
    if (tid == 0) {
        float s = 0.f;
        #pragma unroll
        for (int w = 0; w < 8; w++) s += s_tmp[w];
        s_tmp[0] = sqrtf(s);
    }
    __syncthreads();
    const float qn = s_tmp[0];
    __syncthreads();

    float acc[CPT];
    #pragma unroll
    for (int i = 0; i < CPT; i++) acc[i] = 0.f;
    float m = -1e30f;
    float l = 0.f;

    // double-buffered row registers: RB rows x 2 float4 each
    float4 bA0[RB], bA1[RB], bB0[RB], bB1[RB];

#define LOAD_BATCH(v0, v1, batch)                                             \
    {                                                                         \
        _Pragma("unroll")                                                     \
        for (int r = 0; r < RB; r++) {                                        \
            const float4* rp = reinterpret_cast<const float4*>(               \
                A + ((size_t)(batch) * RB + r) * D) + tid * 2;                \
            v0[r] = rp[0];                                                    \
            v1[r] = rp[1];                                                    \
        }                                                                     \
    }

#define PROCESS(v0, v1)                                                       \
    {                                                                         \
        float dt[RB], sq[RB];                                                 \
        _Pragma("unroll")                                                     \
        for (int r = 0; r < RB; r++) {                                        \
            float d = v0[r].x * qv[0] + v0[r].y * qv[1] +                     \
                      v0[r].z * qv[2] + v0[r].w * qv[3] +                     \
                      v1[r].x * qv[4] + v1[r].y * qv[5] +                     \
                      v1[r].z * qv[6] + v1[r].w * qv[7];                      \
            float s = v0[r].x * v0[r].x + v0[r].y * v0[r].y +                 \
                      v0[r].z * v0[r].z + v0[r].w * v0[r].w +                 \
                      v1[r].x * v1[r].x + v1[r].y * v1[r].y +                 \
                      v1[r].z * v1[r].z + v1[r].w * v1[r].w;                  \
            dt[r] = d; sq[r] = s;                                             \
        }                                                                     \
        _Pragma("unroll")                                                     \
        for (int r = 0; r < RB; r++) {                                        \
            _Pragma("unroll")                                                 \
            for (int o = 16; o; o >>= 1) {                                    \
                dt[r] += __shfl_xor_sync(0xffffffffu, dt[r], o);              \
                sq[r] += __shfl_xor_sync(0xffffffffu, sq[r], o);              \
            }                                                                 \
        }                                                                     \
        if (lane == 0) {                                                      \
            _Pragma("unroll")                                                 \
            for (int r = 0; r < RB; r++) {                                    \
                s_dot[wid][r] = dt[r]; s_sq[wid][r] = sq[r];                  \
            }                                                                 \
        }                                                                     \
        __syncthreads();                                                      \
        if (tid < RB) {                                                       \
            float d = 0.f, s = 0.f;                                           \
            _Pragma("unroll")                                                 \
            for (int w = 0; w < 8; w++) { d += s_dot[w][tid]; s += s_sq[w][tid]; } \
            s_logit[tid] = (d / fmaxf(sqrtf(s) * qn, EPS)) * INV_T;           \
        }                                                                     \
        __syncthreads();                                                      \
        _Pragma("unroll")                                                     \
        for (int r = 0; r < RB; r++) {                                        \
            const float lg = s_logit[r];                                      \
            const float mn = fmaxf(m, lg);                                    \
            const float cs = __expf(m - mn);                                  \
            const float w  = __expf(lg - mn);                                 \
            m = mn;                                                           \
            l = l * cs + w;                                                   \
            acc[0] = acc[0] * cs + w * v0[r].x;                               \
            acc[1] = acc[1] * cs + w * v0[r].y;                               \
            acc[2] = acc[2] * cs + w * v0[r].z;                               \
            acc[3] = acc[3] * cs + w * v0[r].w;                               \
            acc[4] = acc[4] * cs + w * v1[r].x;                               \
            acc[5] = acc[5] * cs + w * v1[r].y;                               \
            acc[6] = acc[6] * cs + w * v1[r].z;                               \
            acc[7] = acc[7] * cs + w * v1[r].w;                               \
        }                                                                     \
    }

    // --- grid-stride pipeline over batches, unrolled x2 for reg buffers ---
    int batch = blockIdx.x;
    bool valid = (batch < NBATCH);
    if (valid) LOAD_BATCH(bA0, bA1, batch);

    while (valid) {
        int nb = batch + NBLK;
        bool vnext = (nb < NBATCH);
        if (vnext) LOAD_BATCH(bB0, bB1, nb);   // prefetch flies over barriers
        PROCESS(bA0, bA1);
        batch = nb; valid = vnext;
        if (!valid) break;

        nb = batch + NBLK;
        vnext = (nb < NBATCH);
        if (vnext) LOAD_BATCH(bA0, bA1, nb);
        PROCESS(bB0, bB1);
        batch = nb; valid = vnext;
    }

    if (tid == 0) { g_pm[blockIdx.x] = m; g_pl[blockIdx.x] = l; }
    float4* pa = reinterpret_cast<float4*>(g_pacc + (size_t)blockIdx.x * D) + tid * 2;
    pa[0] = make_float4(acc[0], acc[1], acc[2], acc[3]);
    pa[1] = make_float4(acc[4], acc[5], acc[6], acc[7]);
#undef LOAD_BATCH
#undef PROCESS
}

// ---------------------------------------------------------------------------
// Finalize 1 (single block): zero the output AND compute per-block scales
// via a global log-sum-exp merge over the 296 partials.
// ---------------------------------------------------------------------------
__global__ __launch_bounds__(NT) void dsdm_scales(float* __restrict__ out) {
    __shared__ float s_red[NT];
    const int tid = threadIdx.x;

    // zero output (harness poisons it; dsdm_out accumulates with atomics)
    #pragma unroll
    for (int i = 0; i < D / NT; i++) out[tid + i * NT] = 0.f;

    float mloc = -1e30f;
    for (int b = tid; b < NBLK; b += NT) mloc = fmaxf(mloc, g_pm[b]);
    s_red[tid] = mloc;
    __syncthreads();
    for (int o = NT / 2; o; o >>= 1) {
        if (tid < o) s_red[tid] = fmaxf(s_red[tid], s_red[tid + o]);
        __syncthreads();
    }
    const float M = s_red[0];
    __syncthreads();

    float lloc = 0.f;
    for (int b = tid; b < NBLK; b += NT) lloc += __expf(g_pm[b] - M) * g_pl[b];
    s_red[tid] = lloc;
    __syncthreads();
    for (int o = NT / 2; o; o >>= 1) {
        if (tid < o) s_red[tid] += s_red[tid + o];
        __syncthreads();
    }
    const float L = s_red[0];
    __syncthreads();

    const float invL = 1.0f / L;
    for (int b = tid; b < NBLK; b += NT) g_scale[b] = __expf(g_pm[b] - M) * invL;
}

// ---------------------------------------------------------------------------
// Finalize 2: grid (D/NT, NBY) = (8, 37) -> 296 blocks. Each block sums
// BCH=8 partials for its 256 columns (coalesced, L2-hot) and REDG-adds.
// ---------------------------------------------------------------------------
__global__ __launch_bounds__(NT) void dsdm_out(float* __restrict__ out) {
    const int col = blockIdx.x * NT + threadIdx.x;
    const int b0  = blockIdx.y * BCH;
    float s = 0.f;
    #pragma unroll
    for (int j = 0; j < BCH; j++) {
        s += g_scale[b0 + j] * g_pacc[(size_t)(b0 + j) * D + col];
    }
    atomicAdd(&out[col], s);
}

extern "C" void kernel_launch(void* const* d_in, const int* in_sizes, int n_in,
                              void* d_out, int out_size) {
    const float* addresses = (const float*)d_in[0];   // [131072, 2048] f32
    const float* query     = (const float*)d_in[1];   // [2048] f32
    float* out = (float*)d_out;                       // [2048] f32

    dsdm_main<<<NBLK, NT>>>(addresses, query);
    dsdm_scales<<<1, NT>>>(out);
    dsdm_out<<<dim3(D / NT, NBY), NT>>>(out);
}